// round 7
// baseline (speedup 1.0000x reference)
#include <cuda_runtime.h>
#include <cstdint>

#define N_NODES 100000
#define D_IN    512
#define D_HID   256
#define D_OUT   32

// Scratch (device globals: no runtime allocation allowed)
__device__ float g_x[(size_t)N_NODES * D_OUT];   // 12.8 MB
__device__ float g_w1t[D_HID * D_IN];            // W1^T, tf32-rounded

// ---------------------------------------------------------------------------
__device__ __forceinline__ float tf32_rna(float x) {
    uint32_t u;
    asm("cvt.rna.tf32.f32 %0, %1;" : "=r"(u) : "f"(x));
    return __uint_as_float(u);
}

__device__ __forceinline__ void mma_tf32(
    float& d0, float& d1, float& d2, float& d3,
    float a0, float a1, float a2, float a3,
    float b0, float b1)
{
    asm volatile(
        "mma.sync.aligned.m16n8k8.row.col.f32.tf32.tf32.f32 "
        "{%0,%1,%2,%3},{%4,%5,%6,%7},{%8,%9},{%0,%1,%2,%3};"
        : "+f"(d0), "+f"(d1), "+f"(d2), "+f"(d3)
        : "r"(__float_as_uint(a0)), "r"(__float_as_uint(a1)),
          "r"(__float_as_uint(a2)), "r"(__float_as_uint(a3)),
          "r"(__float_as_uint(b0)), "r"(__float_as_uint(b1)));
}

__device__ __forceinline__ void red_v2(float* p, float v0, float v1) {
    asm volatile("red.global.add.v2.f32 [%0], {%1, %2};"
                 :: "l"(p), "f"(v0), "f"(v1) : "memory");
}

// ---------------------------------------------------------------------------
// Prep: W1[k][n] -> g_w1t[n][k], tf32-rounded. grid(16,8), block(32,8)
// ---------------------------------------------------------------------------
__global__ void prep_w1_kernel(const float* __restrict__ W1) {
    __shared__ float tile[32][33];
    const int tx = threadIdx.x;
    const int ty = threadIdx.y;
    const int kb = blockIdx.x * 32;
    const int nb = blockIdx.y * 32;
#pragma unroll
    for (int i = 0; i < 4; i++) {
        int k = ty + i * 8;
        tile[k][tx] = W1[(size_t)(kb + k) * D_HID + nb + tx];
    }
    __syncthreads();
#pragma unroll
    for (int i = 0; i < 4; i++) {
        int n = ty + i * 8;
        g_w1t[(size_t)(nb + n) * D_IN + kb + tx] = tf32_rna(tile[tx][n]);
    }
}

// ---------------------------------------------------------------------------
// Init: out = 0 (harness poisons d_out)
// ---------------------------------------------------------------------------
__global__ void init_kernel(float4* out, int n4_out)
{
    int i = blockIdx.x * blockDim.x + threadIdx.x;
    if (i < n4_out) out[i] = make_float4(0.f, 0.f, 0.f, 0.f);
}

// ---------------------------------------------------------------------------
// Fused GEMM: X[m0:m0+128, :] = relu(F @ W1 + b1) @ W2 + b2   (FULL N=256)
// CTA 128x256x32, 512 threads, 16 warps (4M x 4N), warp tile 32x64.
// k-permuted smem: c -> (c&3)*8 + (c>>2), row stride 36 floats.
// SMEM (floats): A0 @0  A1 @4608  B0 @9216 (9216)  B1 @18432
//                w2p @27648 (9216)  h-extra @36864 (9216)  = 46080 fl
// Epilogue: relu(h) 128x256 -> 8 k-perm blocks (A0,A1,B0,B1 + extra),
// X = h @ W2p via mma, direct store (+b2).
// ---------------------------------------------------------------------------
#define G1_BK    32
#define G1_KIT   (D_IN / G1_BK)      // 16
#define G1_LD    36
#define HBLK     4608                // 128*36 floats (one 32-col block)
#define OFF_B    (2 * HBLK)          // 9216
#define B_BUF    9216                // 256*36
#define OFF_W2P  (OFF_B + 2 * B_BUF) // 27648
#define W2P_KB   1152                // 32*36
#define OFF_HX   (OFF_W2P + 8 * W2P_KB)  // 36864
#define G1_SMEM  ((OFF_HX + 2 * HBLK) * 4)   // 184320 bytes

__device__ __forceinline__ float* hblk_ptr(float* sm, int b) {
    return (b < 6) ? (sm + b * HBLK) : (sm + OFF_HX + (b - 6) * HBLK);
}

__global__ __launch_bounds__(512, 1) void gemm_fused_kernel(
    const float* __restrict__ F,
    const float* __restrict__ b1,
    const float* __restrict__ W2,
    const float* __restrict__ b2)
{
    extern __shared__ float sm[];
    float* w2p = sm + OFF_W2P;

    const int t    = threadIdx.x;
    const int lane = t & 31;
    const int wid  = t >> 5;           // 0..15
    const int wm   = wid & 3;          // warp M (0..3)
    const int wn   = wid >> 2;         // warp N (0..3)
    const int g    = lane >> 2;        // 0..7
    const int tig  = lane & 3;         // 0..3

    const int m0 = blockIdx.x * 128;

    // ---- pre-permute W2[0:256, 0:32] into w2p (tf32-rounded) ----
#pragma unroll
    for (int i = 0; i < 16; i++) {
        int idx = t + i * 512;                  // 0..8191
        int c   = idx >> 5;                     // h-col 0..255
        int np  = idx & 31;                     // out col
        float v = tf32_rna(W2[(size_t)c * D_OUT + np]);
        int cc  = c & 31;
        int pos = (cc & 3) * 8 + (cc >> 2);
        w2p[(c >> 5) * W2P_KB + np * G1_LD + pos] = v;
    }

    // ---- staging: A row = t>>2 (2 float4), B row = t>>1 (4 float4) ----
    const int arow_l = t >> 2;
    const int kqa    = (t & 3) * 8;
    const int brow_l = t >> 1;
    const int kqb    = (t & 1) * 16;

    int arow = m0 + arow_l;
    if (arow >= N_NODES) arow = N_NODES - 1;   // clamp; stores guarded
    const float* Ag = F + (size_t)arow * D_IN + kqa;
    const float* Bg = g_w1t + (size_t)brow_l * D_IN + kqb;

    const int pa = arow_l * G1_LD + 2 * (t & 3);
    const int pb = brow_l * G1_LD + 4 * (t & 1);

    float4 ra[2], rb[4];
#pragma unroll
    for (int q = 0; q < 2; q++) ra[q] = *(const float4*)(Ag + q * 4);
#pragma unroll
    for (int q = 0; q < 4; q++) rb[q] = *(const float4*)(Bg + q * 4);

    {
        float* As = sm;
        float* Bs = sm + OFF_B;
#pragma unroll
        for (int q = 0; q < 2; q++) {
            As[pa + q + 0 ] = ra[q].x;
            As[pa + q + 8 ] = ra[q].y;
            As[pa + q + 16] = ra[q].z;
            As[pa + q + 24] = ra[q].w;
        }
#pragma unroll
        for (int q = 0; q < 4; q++) {
            Bs[pb + q + 0 ] = rb[q].x;
            Bs[pb + q + 8 ] = rb[q].y;
            Bs[pb + q + 16] = rb[q].z;
            Bs[pb + q + 24] = rb[q].w;
        }
    }
    __syncthreads();

    float acc[2][8][4];
#pragma unroll
    for (int i = 0; i < 2; i++)
#pragma unroll
        for (int j = 0; j < 8; j++)
#pragma unroll
            for (int c = 0; c < 4; c++) acc[i][j][c] = 0.f;

    const int am = wm * 32;
    const int bn = wn * 64;

    for (int kb = 0; kb < G1_KIT; kb++) {
        if (kb + 1 < G1_KIT) {
            const float* pA = Ag + (kb + 1) * G1_BK;
            const float* pB = Bg + (kb + 1) * G1_BK;
#pragma unroll
            for (int q = 0; q < 2; q++) ra[q] = *(const float4*)(pA + q * 4);
#pragma unroll
            for (int q = 0; q < 4; q++) rb[q] = *(const float4*)(pB + q * 4);
        }

        const float* As = sm + (kb & 1) * HBLK;
        const float* Bs = sm + OFF_B + (kb & 1) * B_BUF;

#pragma unroll
        for (int j = 0; j < 2; j++) {
            float4 afl[2], afh[2];
#pragma unroll
            for (int mt = 0; mt < 2; mt++) {
                int r = am + mt * 16 + g;
                afl[mt] = *(const float4*)(As + r * G1_LD + tig * 8 + j * 4);
                afh[mt] = *(const float4*)(As + (r + 8) * G1_LD + tig * 8 + j * 4);
            }
#pragma unroll
            for (int nt = 0; nt < 8; nt++) {
                int n = bn + nt * 8 + g;
                float4 bf = *(const float4*)(Bs + n * G1_LD + tig * 8 + j * 4);
#pragma unroll
                for (int mt = 0; mt < 2; mt++) {
                    mma_tf32(acc[mt][nt][0], acc[mt][nt][1],
                             acc[mt][nt][2], acc[mt][nt][3],
                             afl[mt].x, afh[mt].x, afl[mt].y, afh[mt].y,
                             bf.x, bf.y);
                    mma_tf32(acc[mt][nt][0], acc[mt][nt][1],
                             acc[mt][nt][2], acc[mt][nt][3],
                             afl[mt].z, afh[mt].z, afl[mt].w, afh[mt].w,
                             bf.z, bf.w);
                }
            }
        }

        if (kb + 1 < G1_KIT) {
            float* Aw = sm + ((kb + 1) & 1) * HBLK;
            float* Bw = sm + OFF_B + ((kb + 1) & 1) * B_BUF;
#pragma unroll
            for (int q = 0; q < 2; q++) {
                Aw[pa + q + 0 ] = ra[q].x;
                Aw[pa + q + 8 ] = ra[q].y;
                Aw[pa + q + 16] = ra[q].z;
                Aw[pa + q + 24] = ra[q].w;
            }
#pragma unroll
            for (int q = 0; q < 4; q++) {
                Bw[pb + q + 0 ] = rb[q].x;
                Bw[pb + q + 8 ] = rb[q].y;
                Bw[pb + q + 16] = rb[q].z;
                Bw[pb + q + 24] = rb[q].w;
            }
            __syncthreads();
        }
    }

    // ---- epilogue 1: bias + relu -> 8 k-perm h blocks (tf32) ----
    __syncthreads();
#pragma unroll
    for (int mt = 0; mt < 2; mt++) {
        const int lr = am + mt * 16 + g;
#pragma unroll
        for (int nt = 0; nt < 8; nt++) {
            const int cc0 = nt * 8 + 2 * tig;              // 0..62 within warp
            const int blk = 2 * wn + (cc0 >> 5);
            const int cc  = cc0 & 31;
            const int pos = (cc & 3) * 8 + (cc >> 2);
            float* hb = hblk_ptr(sm, blk);
            const float bx = __ldg(b1 + bn + cc0);
            const float by = __ldg(b1 + bn + cc0 + 1);
            hb[lr * G1_LD + pos]           = tf32_rna(fmaxf(acc[mt][nt][0] + bx, 0.f));
            hb[lr * G1_LD + pos + 8]       = tf32_rna(fmaxf(acc[mt][nt][1] + by, 0.f));
            hb[(lr + 8) * G1_LD + pos]     = tf32_rna(fmaxf(acc[mt][nt][2] + bx, 0.f));
            hb[(lr + 8) * G1_LD + pos + 8] = tf32_rna(fmaxf(acc[mt][nt][3] + by, 0.f));
        }
    }
    __syncthreads();

    // ---- epilogue 2: X = h(128x256) @ W2p(256x32), FINAL (+b2), STG ----
    // 16 warps: wm2 = wid&7 -> m rows [16*wm2,+16); wn2 = wid>>3 -> cols [16*wn2,+16)
    {
        const int wm2 = wid & 7;
        const int wn2 = wid >> 3;
        float xc[2][4];
#pragma unroll
        for (int nt = 0; nt < 2; nt++)
#pragma unroll
            for (int c = 0; c < 4; c++) xc[nt][c] = 0.f;

#pragma unroll
        for (int kb2 = 0; kb2 < 8; kb2++) {
            const float* Ah = hblk_ptr(sm, kb2);
            const float* Wp = w2p + kb2 * W2P_KB;
#pragma unroll
            for (int j = 0; j < 2; j++) {
                float4 al = *(const float4*)(Ah + (wm2 * 16 + g) * G1_LD + tig * 8 + j * 4);
                float4 ah = *(const float4*)(Ah + (wm2 * 16 + g + 8) * G1_LD + tig * 8 + j * 4);
#pragma unroll
                for (int nt = 0; nt < 2; nt++) {
                    float4 bw = *(const float4*)(Wp + (wn2 * 16 + nt * 8 + g) * G1_LD + tig * 8 + j * 4);
                    mma_tf32(xc[nt][0], xc[nt][1], xc[nt][2], xc[nt][3],
                             al.x, ah.x, al.y, ah.y, bw.x, bw.y);
                    mma_tf32(xc[nt][0], xc[nt][1], xc[nt][2], xc[nt][3],
                             al.z, ah.z, al.w, ah.w, bw.z, bw.w);
                }
            }
        }

        const int mrow = m0 + wm2 * 16 + g;
#pragma unroll
        for (int nt = 0; nt < 2; nt++) {
            const int np = wn2 * 16 + nt * 8 + 2 * tig;
            const float bx = __ldg(b2 + np);
            const float by = __ldg(b2 + np + 1);
            if (mrow < N_NODES) {
                float2 v; v.x = xc[nt][0] + bx; v.y = xc[nt][1] + by;
                *(float2*)(g_x + (size_t)mrow * D_OUT + np) = v;
            }
            if (mrow + 8 < N_NODES) {
                float2 v; v.x = xc[nt][2] + bx; v.y = xc[nt][3] + by;
                *(float2*)(g_x + (size_t)(mrow + 8) * D_OUT + np) = v;
            }
        }
    }
}

// ---------------------------------------------------------------------------
// Scatter: out[A_row[e], :] += A_data[e] * X[A_col[e], :]  (v2 reductions)
// ---------------------------------------------------------------------------
__global__ __launch_bounds__(256) void scatter_kernel(
    const float* __restrict__ A_data,
    const int*   __restrict__ A_row,
    const int*   __restrict__ A_col,
    float*       __restrict__ out,
    int n_edges)
{
    int idx = blockIdx.x * blockDim.x + threadIdx.x;
    int e = idx >> 3;
    int q = idx & 7;
    if (e >= n_edges) return;

    float a = __ldg(A_data + e);
    int   r = __ldg(A_row + e);
    int   c = __ldg(A_col + e);

    float4 xv = *(const float4*)(g_x + (size_t)c * D_OUT + q * 4);
    float* o  = out + (size_t)r * D_OUT + q * 4;
    red_v2(o + 0, a * xv.x, a * xv.y);
    red_v2(o + 2, a * xv.z, a * xv.w);
}

// ---------------------------------------------------------------------------
extern "C" void kernel_launch(void* const* d_in, const int* in_sizes, int n_in,
                              void* d_out, int out_size)
{
    const float* F      = (const float*)d_in[0];
    const float* A_data = (const float*)d_in[1];
    const float* W1     = (const float*)d_in[2];
    const float* b1     = (const float*)d_in[3];
    const float* W2     = (const float*)d_in[4];
    const float* b2     = (const float*)d_in[5];
    const int*   A_row  = (const int*)d_in[6];
    const int*   A_col  = (const int*)d_in[7];
    float* out = (float*)d_out;

    const int n_edges = in_sizes[1];

    cudaFuncSetAttribute(gemm_fused_kernel,
                         cudaFuncAttributeMaxDynamicSharedMemorySize, G1_SMEM);

    // W1 transpose + tf32 rounding
    prep_w1_kernel<<<dim3(D_IN / 32, D_HID / 32), dim3(32, 8)>>>(W1);

    // out = 0
    const int n4_out = out_size / 4;
    init_kernel<<<(n4_out + 255) / 256, 256>>>((float4*)out, n4_out);

    // Fused GEMM (full-N CTA; X stored directly)
    gemm_fused_kernel<<<(N_NODES + 127) / 128, 512, G1_SMEM>>>(F, b1, W2, b2);

    // Scatter
    long long tot = (long long)n_edges * 8;
    int blocks = (int)((tot + 255) / 256);
    scatter_kernel<<<blocks, 256>>>(A_data, A_row, A_col, out, n_edges);
}

// round 9
// speedup vs baseline: 1.8035x; 1.8035x over previous
#include <cuda_runtime.h>
#include <cuda_fp16.h>
#include <cstdint>

#define N_NODES 100000
#define D_IN    512
#define D_HID   256
#define D_OUT   32

// Scratch (device globals: no runtime allocation allowed)
__device__ float  g_x[(size_t)N_NODES * D_OUT];   // 12.8 MB
__device__ __half g_w1t_h[D_HID * D_IN];          // W1^T in fp16 (256 KB)

// ---------------------------------------------------------------------------
__device__ __forceinline__ void mma_f16(
    float& d0, float& d1, float& d2, float& d3,
    uint32_t a0, uint32_t a1, uint32_t a2, uint32_t a3,
    uint32_t b0, uint32_t b1)
{
    asm volatile(
        "mma.sync.aligned.m16n8k16.row.col.f32.f16.f16.f32 "
        "{%0,%1,%2,%3},{%4,%5,%6,%7},{%8,%9},{%0,%1,%2,%3};"
        : "+f"(d0), "+f"(d1), "+f"(d2), "+f"(d3)
        : "r"(a0), "r"(a1), "r"(a2), "r"(a3), "r"(b0), "r"(b1));
}

__device__ __forceinline__ void red_v2(float* p, float v0, float v1) {
    asm volatile("red.global.add.v2.f32 [%0], {%1, %2};"
                 :: "l"(p), "f"(v0), "f"(v1) : "memory");
}

__device__ __forceinline__ uint32_t h2bits(float lo, float hi) {
    __half2 h = __floats2half2_rn(lo, hi);
    return *reinterpret_cast<uint32_t*>(&h);
}

// ---------------------------------------------------------------------------
// Prep: W1[k][n] -> g_w1t_h[n][k] (fp16). grid(16,8), block(32,8)
// ---------------------------------------------------------------------------
__global__ void prep_w1_kernel(const float* __restrict__ W1) {
    __shared__ float tile[32][33];
    const int tx = threadIdx.x;
    const int ty = threadIdx.y;
    const int kb = blockIdx.x * 32;
    const int nb = blockIdx.y * 32;
#pragma unroll
    for (int i = 0; i < 4; i++) {
        int k = ty + i * 8;
        tile[k][tx] = W1[(size_t)(kb + k) * D_HID + nb + tx];
    }
    __syncthreads();
#pragma unroll
    for (int i = 0; i < 4; i++) {
        int n = ty + i * 8;
        g_w1t_h[(size_t)(nb + n) * D_IN + kb + tx] = __float2half_rn(tile[tx][n]);
    }
}

// ---------------------------------------------------------------------------
// Init: g_x[n][c] = b2[c] (epilogue accumulates); out = 0
// ---------------------------------------------------------------------------
__global__ void init_kernel(float4* out, int n4_out, const float* __restrict__ b2)
{
    int i = blockIdx.x * blockDim.x + threadIdx.x;
    if (i < n4_out) {
        out[i] = make_float4(0.f, 0.f, 0.f, 0.f);
    } else {
        int j = i - n4_out;
        if (j < N_NODES * (D_OUT / 4)) {
            int c = (j * 4) & (D_OUT - 1);
            float4 v;
            v.x = __ldg(b2 + c);     v.y = __ldg(b2 + c + 1);
            v.z = __ldg(b2 + c + 2); v.w = __ldg(b2 + c + 3);
            ((float4*)g_x)[j] = v;
        }
    }
}

// ---------------------------------------------------------------------------
// Fused GEMM (fp16): X += relu(F@W1+b1)[:, n0:n0+128] @ W2[n0:n0+128, :]
// CTA 128x128x32, 512 threads, 16 warps (4M x 4N), warp tile 32x32.
// SMEM rows: 16 u32 (32 half k-elements), NO padding (16B-aligned uint4).
// k-pair c of row r stored at u32 index r*16 + 4*((c&3) ^ ((r>>1)&3)) + (c>>2)
// -> fragment uint4 at chunk (tig ^ (g>>1)) delivers pairs {tig,tig+4,+8,+12};
// stores and loads are bank-conflict-free (verified per 8-lane phase).
// Layout (u32): As0 @0  As1 @2048  Bs0 @4096  Bs1 @6144  w2p @8192 (2048)
//               total 10240 u32 = 40 KB static.
// ---------------------------------------------------------------------------
#define G1_BK   32
#define G1_KIT  (D_IN / G1_BK)      // 16
#define LDH     16                  // u32 per smem row
#define HBUF    2048                // 128*16 u32 per buffer
#define OFF_W2P 8192
#define W2P_KB  512                 // 32*16 u32 per k-block

__global__ __launch_bounds__(512) void gemm_fused_kernel(
    const float* __restrict__ F,
    const float* __restrict__ b1,
    const float* __restrict__ W2)
{
    __shared__ uint32_t smh[10240];

    const int t    = threadIdx.x;
    const int lane = t & 31;
    const int wid  = t >> 5;           // 0..15
    const int wm   = wid & 3;          // warp M (0..3)
    const int wn   = wid >> 2;         // warp N (0..3)
    const int g    = lane >> 2;        // 0..7
    const int tig  = lane & 3;         // 0..3
    const int tigsw = ((tig ^ (g >> 1)) & 3) * 4;   // fragment chunk offset

    const int n0 = blockIdx.x * 128;   // N fastest -> F L2 reuse
    const int m0 = blockIdx.y * 128;

    // ---- pre-permute W2 slice [n0:n0+128, 0:32] into w2p (fp16) ----
#pragma unroll
    for (int i = 0; i < 4; i++) {
        int idx   = t + i * 512;            // 0..2047
        int cpair = idx >> 5;               // h-col pair 0..63
        int np    = idx & 31;               // out col
        int c     = cpair * 2;
        float w0 = W2[(size_t)(n0 + c) * D_OUT + np];
        float w1 = W2[(size_t)(n0 + c + 1) * D_OUT + np];
        int kb    = cpair >> 4;             // k-block 0..3
        int cp    = cpair & 15;             // pair within block
        int chunk = (cp & 3) ^ ((np >> 1) & 3);
        int intra = cp >> 2;
        smh[OFF_W2P + kb * W2P_KB + np * LDH + chunk * 4 + intra] = h2bits(w0, w1);
    }

    // ---- staging: row = t>>2, q = t&3 covers k [8q, 8q+8) (pairs 4q..4q+3)
    const int srow = t >> 2;
    const int q    = t & 3;
    const int sws  = (srow >> 1) & 3;

    int arow = m0 + srow;
    if (arow >= N_NODES) arow = N_NODES - 1;   // clamp; outputs guarded
    const float*  Ag = F + (size_t)arow * D_IN + q * 8;
    const __half* Bg = g_w1t_h + (size_t)(n0 + srow) * D_IN + q * 8;

    // pair c = 4q + i: chunk = i, intra = q -> index = 4*(i^sws) + q
    const int st0 = srow * LDH + ((0 ^ sws) * 4) + q;
    const int st1 = srow * LDH + ((1 ^ sws) * 4) + q;
    const int st2 = srow * LDH + ((2 ^ sws) * 4) + q;
    const int st3 = srow * LDH + ((3 ^ sws) * 4) + q;

    float4 va0, va1; uint4 vb;
    va0 = *(const float4*)(Ag);
    va1 = *(const float4*)(Ag + 4);
    vb  = *(const uint4*)(Bg);

    {
        uint32_t* As = smh;
        uint32_t* Bs = smh + 4096;
        As[st0] = h2bits(va0.x, va0.y);
        As[st1] = h2bits(va0.z, va0.w);
        As[st2] = h2bits(va1.x, va1.y);
        As[st3] = h2bits(va1.z, va1.w);
        Bs[st0] = vb.x;
        Bs[st1] = vb.y;
        Bs[st2] = vb.z;
        Bs[st3] = vb.w;
    }
    __syncthreads();

    float acc[2][4][4];
#pragma unroll
    for (int i = 0; i < 2; i++)
#pragma unroll
        for (int j = 0; j < 4; j++)
#pragma unroll
            for (int c = 0; c < 4; c++) acc[i][j][c] = 0.f;

    const int am = wm * 32;
    const int bn = wn * 32;

    for (int kb = 0; kb < G1_KIT; kb++) {
        if (kb + 1 < G1_KIT) {
            const float*  pA = Ag + (kb + 1) * G1_BK;
            const __half* pB = Bg + (kb + 1) * G1_BK;
            va0 = *(const float4*)(pA);
            va1 = *(const float4*)(pA + 4);
            vb  = *(const uint4*)(pB);
        }

        const uint32_t* As = smh + (kb & 1) * HBUF;
        const uint32_t* Bs = smh + 4096 + (kb & 1) * HBUF;

        uint4 alo[2], ahi[2], bf[4];
#pragma unroll
        for (int mt = 0; mt < 2; mt++) {
            int r = am + mt * 16 + g;
            alo[mt] = *(const uint4*)(As + r * LDH + tigsw);
            ahi[mt] = *(const uint4*)(As + (r + 8) * LDH + tigsw);
        }
#pragma unroll
        for (int nt = 0; nt < 4; nt++) {
            int n = bn + nt * 8 + g;
            bf[nt] = *(const uint4*)(Bs + n * LDH + tigsw);
        }
#pragma unroll
        for (int mt = 0; mt < 2; mt++) {
#pragma unroll
            for (int nt = 0; nt < 4; nt++) {
                // j = 0 (k 0..15): pairs tig, tig+4
                mma_f16(acc[mt][nt][0], acc[mt][nt][1],
                        acc[mt][nt][2], acc[mt][nt][3],
                        alo[mt].x, ahi[mt].x, alo[mt].y, ahi[mt].y,
                        bf[nt].x,  bf[nt].y);
                // j = 1 (k 16..31): pairs tig+8, tig+12
                mma_f16(acc[mt][nt][0], acc[mt][nt][1],
                        acc[mt][nt][2], acc[mt][nt][3],
                        alo[mt].z, ahi[mt].z, alo[mt].w, ahi[mt].w,
                        bf[nt].z,  bf[nt].w);
            }
        }

        if (kb + 1 < G1_KIT) {
            uint32_t* Aw = smh + ((kb + 1) & 1) * HBUF;
            uint32_t* Bw = smh + 4096 + ((kb + 1) & 1) * HBUF;
            Aw[st0] = h2bits(va0.x, va0.y);
            Aw[st1] = h2bits(va0.z, va0.w);
            Aw[st2] = h2bits(va1.x, va1.y);
            Aw[st3] = h2bits(va1.z, va1.w);
            Bw[st0] = vb.x;
            Bw[st1] = vb.y;
            Bw[st2] = vb.z;
            Bw[st3] = vb.w;
            __syncthreads();
        }
    }

    // ---- epilogue 1: bias + relu -> 4 h blocks (fp16, swizzled layout) ----
    __syncthreads();   // all fragment reads complete before overwrite
#pragma unroll
    for (int mt = 0; mt < 2; mt++) {
        const int lr = am + mt * 16 + g;
#pragma unroll
        for (int nt = 0; nt < 4; nt++) {
            // col pair c_h = nt*4 + tig: chunk = tig, intra = nt
            const int cc0 = nt * 8 + 2 * tig;
            const int pos = tigsw + nt;          // 4*(tig^(g>>1)) + nt
            const float bx = __ldg(b1 + n0 + bn + cc0);
            const float by = __ldg(b1 + n0 + bn + cc0 + 1);
            uint32_t* hb = smh + wn * HBUF;      // h block = wn
            hb[lr * LDH + pos] =
                h2bits(fmaxf(acc[mt][nt][0] + bx, 0.f),
                       fmaxf(acc[mt][nt][1] + by, 0.f));
            hb[(lr + 8) * LDH + pos] =
                h2bits(fmaxf(acc[mt][nt][2] + bx, 0.f),
                       fmaxf(acc[mt][nt][3] + by, 0.f));
        }
    }
    __syncthreads();

    // ---- epilogue 2: X partial = h(128x128) @ W2p(128x32) via fp16 mma ----
    // wm2 = wid&7 -> m rows [16*wm2,+16); wn2 = wid>>3 -> out cols [16*wn2,+16)
    {
        const int wm2 = wid & 7;
        const int wn2 = wid >> 3;
        float xc[2][4];
#pragma unroll
        for (int nt = 0; nt < 2; nt++)
#pragma unroll
            for (int c = 0; c < 4; c++) xc[nt][c] = 0.f;

#pragma unroll
        for (int kb2 = 0; kb2 < 4; kb2++) {
            const uint32_t* Ah = smh + kb2 * HBUF;
            const uint32_t* Wp = smh + OFF_W2P + kb2 * W2P_KB;
            uint4 alo = *(const uint4*)(Ah + (wm2 * 16 + g) * LDH + tigsw);
            uint4 ahi = *(const uint4*)(Ah + (wm2 * 16 + 8 + g) * LDH + tigsw);
#pragma unroll
            for (int nt = 0; nt < 2; nt++) {
                uint4 bw = *(const uint4*)(Wp + (wn2 * 16 + nt * 8 + g) * LDH + tigsw);
                mma_f16(xc[nt][0], xc[nt][1], xc[nt][2], xc[nt][3],
                        alo.x, ahi.x, alo.y, ahi.y, bw.x, bw.y);
                mma_f16(xc[nt][0], xc[nt][1], xc[nt][2], xc[nt][3],
                        alo.z, ahi.z, alo.w, ahi.w, bw.z, bw.w);
            }
        }

        const int mrow = m0 + wm2 * 16 + g;
#pragma unroll
        for (int nt = 0; nt < 2; nt++) {
            const int np = wn2 * 16 + nt * 8 + 2 * tig;
            if (mrow < N_NODES)
                red_v2(g_x + (size_t)mrow * D_OUT + np, xc[nt][0], xc[nt][1]);
            if (mrow + 8 < N_NODES)
                red_v2(g_x + (size_t)(mrow + 8) * D_OUT + np, xc[nt][2], xc[nt][3]);
        }
    }
}

// ---------------------------------------------------------------------------
// Scatter: out[A_row[e], :] += A_data[e] * X[A_col[e], :]  (v2 reductions)
// ---------------------------------------------------------------------------
__global__ __launch_bounds__(256) void scatter_kernel(
    const float* __restrict__ A_data,
    const int*   __restrict__ A_row,
    const int*   __restrict__ A_col,
    float*       __restrict__ out,
    int n_edges)
{
    int idx = blockIdx.x * blockDim.x + threadIdx.x;
    int e = idx >> 3;
    int qq = idx & 7;
    if (e >= n_edges) return;

    float a = __ldg(A_data + e);
    int   r = __ldg(A_row + e);
    int   c = __ldg(A_col + e);

    float4 xv = *(const float4*)(g_x + (size_t)c * D_OUT + qq * 4);
    float* o  = out + (size_t)r * D_OUT + qq * 4;
    red_v2(o + 0, a * xv.x, a * xv.y);
    red_v2(o + 2, a * xv.z, a * xv.w);
}

// ---------------------------------------------------------------------------
extern "C" void kernel_launch(void* const* d_in, const int* in_sizes, int n_in,
                              void* d_out, int out_size)
{
    const float* F      = (const float*)d_in[0];
    const float* A_data = (const float*)d_in[1];
    const float* W1     = (const float*)d_in[2];
    const float* b1     = (const float*)d_in[3];
    const float* W2     = (const float*)d_in[4];
    const float* b2     = (const float*)d_in[5];
    const int*   A_row  = (const int*)d_in[6];
    const int*   A_col  = (const int*)d_in[7];
    float* out = (float*)d_out;

    const int n_edges = in_sizes[1];

    // W1 transpose + fp16 conversion
    prep_w1_kernel<<<dim3(D_IN / 32, D_HID / 32), dim3(32, 8)>>>(W1);

    // out = 0, g_x = b2
    const int n4_out = out_size / 4;
    const int n4_x   = N_NODES * D_OUT / 4;
    init_kernel<<<(n4_out + n4_x + 255) / 256, 256>>>((float4*)out, n4_out, b2);

    // Fused GEMM (fp16 tensor cores; N fastest for F L2 reuse)
    dim3 g1(D_HID / 128, (N_NODES + 127) / 128);
    gemm_fused_kernel<<<g1, 512>>>(F, b1, W2);

    // Scatter
    long long tot = (long long)n_edges * 8;
    int blocks = (int)((tot + 255) / 256);
    scatter_kernel<<<blocks, 256>>>(A_data, A_row, A_col, out, n_edges);
}

// round 10
// speedup vs baseline: 1.9185x; 1.0638x over previous
#include <cuda_runtime.h>
#include <cuda_fp16.h>
#include <cstdint>

#define N_NODES 100000
#define D_IN    512
#define D_HID   256
#define D_OUT   32

// Scratch (device globals: no runtime allocation allowed)
__device__ float  g_x[(size_t)N_NODES * D_OUT];   // 12.8 MB
__device__ __half g_w1t_h[D_HID * D_IN];          // W1^T in fp16 (256 KB)

// ---------------------------------------------------------------------------
__device__ __forceinline__ void mma_f16(
    float& d0, float& d1, float& d2, float& d3,
    uint32_t a0, uint32_t a1, uint32_t a2, uint32_t a3,
    uint32_t b0, uint32_t b1)
{
    asm volatile(
        "mma.sync.aligned.m16n8k16.row.col.f32.f16.f16.f32 "
        "{%0,%1,%2,%3},{%4,%5,%6,%7},{%8,%9},{%0,%1,%2,%3};"
        : "+f"(d0), "+f"(d1), "+f"(d2), "+f"(d3)
        : "r"(a0), "r"(a1), "r"(a2), "r"(a3), "r"(b0), "r"(b1));
}

__device__ __forceinline__ void red_v2(float* p, float v0, float v1) {
    asm volatile("red.global.add.v2.f32 [%0], {%1, %2};"
                 :: "l"(p), "f"(v0), "f"(v1) : "memory");
}

__device__ __forceinline__ void red_v4(float* p, float v0, float v1,
                                       float v2, float v3) {
    asm volatile("red.global.add.v4.f32 [%0], {%1, %2, %3, %4};"
                 :: "l"(p), "f"(v0), "f"(v1), "f"(v2), "f"(v3) : "memory");
}

__device__ __forceinline__ uint32_t h2bits(float lo, float hi) {
    __half2 h = __floats2half2_rn(lo, hi);
    return *reinterpret_cast<uint32_t*>(&h);
}

// ---------------------------------------------------------------------------
// Prep: W1[k][n] -> g_w1t_h[n][k] (fp16). grid(16,8), block(32,8)
// ---------------------------------------------------------------------------
__global__ void prep_w1_kernel(const float* __restrict__ W1) {
    __shared__ float tile[32][33];
    const int tx = threadIdx.x;
    const int ty = threadIdx.y;
    const int kb = blockIdx.x * 32;
    const int nb = blockIdx.y * 32;
#pragma unroll
    for (int i = 0; i < 4; i++) {
        int k = ty + i * 8;
        tile[k][tx] = W1[(size_t)(kb + k) * D_HID + nb + tx];
    }
    __syncthreads();
#pragma unroll
    for (int i = 0; i < 4; i++) {
        int n = ty + i * 8;
        g_w1t_h[(size_t)(nb + n) * D_IN + kb + tx] = __float2half_rn(tile[tx][n]);
    }
}

// ---------------------------------------------------------------------------
// Init: g_x[n][c] = b2[c] (epilogue accumulates); out = 0
// ---------------------------------------------------------------------------
__global__ void init_kernel(float4* out, int n4_out, const float* __restrict__ b2)
{
    int i = blockIdx.x * blockDim.x + threadIdx.x;
    if (i < n4_out) {
        out[i] = make_float4(0.f, 0.f, 0.f, 0.f);
    } else {
        int j = i - n4_out;
        if (j < N_NODES * (D_OUT / 4)) {
            int c = (j * 4) & (D_OUT - 1);
            float4 v;
            v.x = __ldg(b2 + c);     v.y = __ldg(b2 + c + 1);
            v.z = __ldg(b2 + c + 2); v.w = __ldg(b2 + c + 3);
            ((float4*)g_x)[j] = v;
        }
    }
}

// ---------------------------------------------------------------------------
// Fused GEMM (fp16): X += relu(F@W1+b1)[:, n0:n0+128] @ W2[n0:n0+128, :]
// CTA 128x128x32, 512 threads, 16 warps (4M x 4N), warp tile 32x32.
// SMEM rows: 16 u32 (32 half k-elements), NO padding (16B-aligned uint4).
// k-pair c of row r stored at u32 index r*16 + 4*((c&3) ^ ((r>>1)&3)) + (c>>2)
// -> fragment uint4 at chunk (tig ^ (g>>1)) delivers pairs {tig,tig+4,+8,+12};
// stores and loads are bank-conflict-free.
// Layout (u32): As0 @0  As1 @2048  Bs0 @4096  Bs1 @6144  w2p @8192 (2048)
//               total 10240 u32 = 40 KB static.
// ---------------------------------------------------------------------------
#define G1_BK   32
#define G1_KIT  (D_IN / G1_BK)      // 16
#define LDH     16                  // u32 per smem row
#define HBUF    2048                // 128*16 u32 per buffer
#define OFF_W2P 8192
#define W2P_KB  512                 // 32*16 u32 per k-block

__global__ __launch_bounds__(512) void gemm_fused_kernel(
    const float* __restrict__ F,
    const float* __restrict__ b1,
    const float* __restrict__ W2)
{
    __shared__ uint32_t smh[10240];

    const int t    = threadIdx.x;
    const int lane = t & 31;
    const int wid  = t >> 5;           // 0..15
    const int wm   = wid & 3;          // warp M (0..3)
    const int wn   = wid >> 2;         // warp N (0..3)
    const int g    = lane >> 2;        // 0..7
    const int tig  = lane & 3;         // 0..3
    const int tigsw = ((tig ^ (g >> 1)) & 3) * 4;   // fragment chunk offset

    const int n0 = blockIdx.x * 128;   // N fastest -> F L2 reuse
    const int m0 = blockIdx.y * 128;

    // ---- pre-permute W2 slice [n0:n0+128, 0:32] into w2p (fp16) ----
#pragma unroll
    for (int i = 0; i < 4; i++) {
        int idx   = t + i * 512;            // 0..2047
        int cpair = idx >> 5;               // h-col pair 0..63
        int np    = idx & 31;               // out col
        int c     = cpair * 2;
        float w0 = W2[(size_t)(n0 + c) * D_OUT + np];
        float w1 = W2[(size_t)(n0 + c + 1) * D_OUT + np];
        int kb    = cpair >> 4;             // k-block 0..3
        int cp    = cpair & 15;             // pair within block
        int chunk = (cp & 3) ^ ((np >> 1) & 3);
        int intra = cp >> 2;
        smh[OFF_W2P + kb * W2P_KB + np * LDH + chunk * 4 + intra] = h2bits(w0, w1);
    }

    // ---- staging: row = t>>2, q = t&3 covers k [8q, 8q+8) (pairs 4q..4q+3)
    const int srow = t >> 2;
    const int q    = t & 3;
    const int sws  = (srow >> 1) & 3;

    int arow = m0 + srow;
    if (arow >= N_NODES) arow = N_NODES - 1;   // clamp; outputs guarded
    const float*  Ag = F + (size_t)arow * D_IN + q * 8;
    const __half* Bg = g_w1t_h + (size_t)(n0 + srow) * D_IN + q * 8;

    // pair c = 4q + i: chunk = i, intra = q -> index = 4*(i^sws) + q
    const int st0 = srow * LDH + ((0 ^ sws) * 4) + q;
    const int st1 = srow * LDH + ((1 ^ sws) * 4) + q;
    const int st2 = srow * LDH + ((2 ^ sws) * 4) + q;
    const int st3 = srow * LDH + ((3 ^ sws) * 4) + q;

    float4 va0, va1; uint4 vb;
    va0 = *(const float4*)(Ag);
    va1 = *(const float4*)(Ag + 4);
    vb  = *(const uint4*)(Bg);

    {
        uint32_t* As = smh;
        uint32_t* Bs = smh + 4096;
        As[st0] = h2bits(va0.x, va0.y);
        As[st1] = h2bits(va0.z, va0.w);
        As[st2] = h2bits(va1.x, va1.y);
        As[st3] = h2bits(va1.z, va1.w);
        Bs[st0] = vb.x;
        Bs[st1] = vb.y;
        Bs[st2] = vb.z;
        Bs[st3] = vb.w;
    }
    __syncthreads();

    float acc[2][4][4];
#pragma unroll
    for (int i = 0; i < 2; i++)
#pragma unroll
        for (int j = 0; j < 4; j++)
#pragma unroll
            for (int c = 0; c < 4; c++) acc[i][j][c] = 0.f;

    const int am = wm * 32;
    const int bn = wn * 32;

#pragma unroll 2
    for (int kb = 0; kb < G1_KIT; kb++) {
        if (kb + 1 < G1_KIT) {
            const float*  pA = Ag + (kb + 1) * G1_BK;
            const __half* pB = Bg + (kb + 1) * G1_BK;
            va0 = *(const float4*)(pA);
            va1 = *(const float4*)(pA + 4);
            vb  = *(const uint4*)(pB);
        }

        const uint32_t* As = smh + (kb & 1) * HBUF;
        const uint32_t* Bs = smh + 4096 + (kb & 1) * HBUF;

        uint4 alo[2], ahi[2], bf[4];
#pragma unroll
        for (int mt = 0; mt < 2; mt++) {
            int r = am + mt * 16 + g;
            alo[mt] = *(const uint4*)(As + r * LDH + tigsw);
            ahi[mt] = *(const uint4*)(As + (r + 8) * LDH + tigsw);
        }
#pragma unroll
        for (int nt = 0; nt < 4; nt++) {
            int n = bn + nt * 8 + g;
            bf[nt] = *(const uint4*)(Bs + n * LDH + tigsw);
        }
#pragma unroll
        for (int mt = 0; mt < 2; mt++) {
#pragma unroll
            for (int nt = 0; nt < 4; nt++) {
                // j = 0 (k 0..15): pairs tig, tig+4
                mma_f16(acc[mt][nt][0], acc[mt][nt][1],
                        acc[mt][nt][2], acc[mt][nt][3],
                        alo[mt].x, ahi[mt].x, alo[mt].y, ahi[mt].y,
                        bf[nt].x,  bf[nt].y);
                // j = 1 (k 16..31): pairs tig+8, tig+12
                mma_f16(acc[mt][nt][0], acc[mt][nt][1],
                        acc[mt][nt][2], acc[mt][nt][3],
                        alo[mt].z, ahi[mt].z, alo[mt].w, ahi[mt].w,
                        bf[nt].z,  bf[nt].w);
            }
        }

        if (kb + 1 < G1_KIT) {
            uint32_t* Aw = smh + ((kb + 1) & 1) * HBUF;
            uint32_t* Bw = smh + 4096 + ((kb + 1) & 1) * HBUF;
            Aw[st0] = h2bits(va0.x, va0.y);
            Aw[st1] = h2bits(va0.z, va0.w);
            Aw[st2] = h2bits(va1.x, va1.y);
            Aw[st3] = h2bits(va1.z, va1.w);
            Bw[st0] = vb.x;
            Bw[st1] = vb.y;
            Bw[st2] = vb.z;
            Bw[st3] = vb.w;
            __syncthreads();
        }
    }

    // ---- epilogue 1: bias + relu -> 4 h blocks (fp16, swizzled layout) ----
    __syncthreads();   // all fragment reads complete before overwrite
#pragma unroll
    for (int mt = 0; mt < 2; mt++) {
        const int lr = am + mt * 16 + g;
#pragma unroll
        for (int nt = 0; nt < 4; nt++) {
            // col pair c_h = nt*4 + tig: chunk = tig, intra = nt
            const int cc0 = nt * 8 + 2 * tig;
            const int pos = tigsw + nt;          // 4*(tig^(g>>1)) + nt
            const float bx = __ldg(b1 + n0 + bn + cc0);
            const float by = __ldg(b1 + n0 + bn + cc0 + 1);
            uint32_t* hb = smh + wn * HBUF;      // h block = wn
            hb[lr * LDH + pos] =
                h2bits(fmaxf(acc[mt][nt][0] + bx, 0.f),
                       fmaxf(acc[mt][nt][1] + by, 0.f));
            hb[(lr + 8) * LDH + pos] =
                h2bits(fmaxf(acc[mt][nt][2] + bx, 0.f),
                       fmaxf(acc[mt][nt][3] + by, 0.f));
        }
    }
    __syncthreads();

    // ---- epilogue 2: X partial = h(128x128) @ W2p(128x32) via fp16 mma ----
    // wm2 = wid&7 -> m rows [16*wm2,+16); wn2 = wid>>3 -> out cols [16*wn2,+16)
    {
        const int wm2 = wid & 7;
        const int wn2 = wid >> 3;
        float xc[2][4];
#pragma unroll
        for (int nt = 0; nt < 2; nt++)
#pragma unroll
            for (int c = 0; c < 4; c++) xc[nt][c] = 0.f;

#pragma unroll
        for (int kb2 = 0; kb2 < 4; kb2++) {
            const uint32_t* Ah = smh + kb2 * HBUF;
            const uint32_t* Wp = smh + OFF_W2P + kb2 * W2P_KB;
            uint4 alo = *(const uint4*)(Ah + (wm2 * 16 + g) * LDH + tigsw);
            uint4 ahi = *(const uint4*)(Ah + (wm2 * 16 + 8 + g) * LDH + tigsw);
#pragma unroll
            for (int nt = 0; nt < 2; nt++) {
                uint4 bw = *(const uint4*)(Wp + (wn2 * 16 + nt * 8 + g) * LDH + tigsw);
                mma_f16(xc[nt][0], xc[nt][1], xc[nt][2], xc[nt][3],
                        alo.x, ahi.x, alo.y, ahi.y, bw.x, bw.y);
                mma_f16(xc[nt][0], xc[nt][1], xc[nt][2], xc[nt][3],
                        alo.z, ahi.z, alo.w, ahi.w, bw.z, bw.w);
            }
        }

        const int mrow = m0 + wm2 * 16 + g;
#pragma unroll
        for (int nt = 0; nt < 2; nt++) {
            const int np = wn2 * 16 + nt * 8 + 2 * tig;
            if (mrow < N_NODES)
                red_v2(g_x + (size_t)mrow * D_OUT + np, xc[nt][0], xc[nt][1]);
            if (mrow + 8 < N_NODES)
                red_v2(g_x + (size_t)(mrow + 8) * D_OUT + np, xc[nt][2], xc[nt][3]);
        }
    }
}

// ---------------------------------------------------------------------------
// Scatter: out[A_row[e], :] += A_data[e] * X[A_col[e], :]
// 8 threads/edge, one red.global.add.v4.f32 each (12.8M L2 atomic ops)
// ---------------------------------------------------------------------------
__global__ __launch_bounds__(256) void scatter_kernel(
    const float* __restrict__ A_data,
    const int*   __restrict__ A_row,
    const int*   __restrict__ A_col,
    float*       __restrict__ out,
    int n_edges)
{
    int idx = blockIdx.x * blockDim.x + threadIdx.x;
    int e = idx >> 3;
    int qq = idx & 7;
    if (e >= n_edges) return;

    float a = __ldg(A_data + e);
    int   r = __ldg(A_row + e);
    int   c = __ldg(A_col + e);

    float4 xv = *(const float4*)(g_x + (size_t)c * D_OUT + qq * 4);
    float* o  = out + (size_t)r * D_OUT + qq * 4;
    red_v4(o, a * xv.x, a * xv.y, a * xv.z, a * xv.w);
}

// ---------------------------------------------------------------------------
extern "C" void kernel_launch(void* const* d_in, const int* in_sizes, int n_in,
                              void* d_out, int out_size)
{
    const float* F      = (const float*)d_in[0];
    const float* A_data = (const float*)d_in[1];
    const float* W1     = (const float*)d_in[2];
    const float* b1     = (const float*)d_in[3];
    const float* W2     = (const float*)d_in[4];
    const float* b2     = (const float*)d_in[5];
    const int*   A_row  = (const int*)d_in[6];
    const int*   A_col  = (const int*)d_in[7];
    float* out = (float*)d_out;

    const int n_edges = in_sizes[1];

    // W1 transpose + fp16 conversion
    prep_w1_kernel<<<dim3(D_IN / 32, D_HID / 32), dim3(32, 8)>>>(W1);

    // out = 0, g_x = b2
    const int n4_out = out_size / 4;
    const int n4_x   = N_NODES * D_OUT / 4;
    init_kernel<<<(n4_out + n4_x + 255) / 256, 256>>>((float4*)out, n4_out, b2);

    // Fused GEMM (fp16 tensor cores; N fastest for F L2 reuse)
    dim3 g1(D_HID / 128, (N_NODES + 127) / 128);
    gemm_fused_kernel<<<g1, 512>>>(F, b1, W2);

    // Scatter
    long long tot = (long long)n_edges * 8;
    int blocks = (int)((tot + 255) / 256);
    scatter_kernel<<<blocks, 256>>>(A_data, A_row, A_col, out, n_edges);
}